// round 4
// baseline (speedup 1.0000x reference)
#include <cuda_runtime.h>
#include <math_constants.h>

#define G 8
#define NB 8192
#define THREADS 256

// Wk transposed: [h][c] = Wk[c][h], 256x512 floats
__device__ float g_WkT[256 * 512];

__global__ void wkT_kernel(const float* __restrict__ Wk) {
    int idx = blockIdx.x * blockDim.x + threadIdx.x;
    if (idx < 512 * 256) {
        int c = idx >> 8;      // 0..511
        int h = idx & 255;     // 0..255
        g_WkT[h * 512 + c] = Wk[idx];
    }
}

// Dynamic smem (floats):
//   bufA : [512][G]  (x concat, later wn)                    4096 f
//   eq   : [512][G]  (ee [0:256), q [256:512)) -> overlay kq 4096 f
//   qbk  : [G]
#define SMEM_FLOATS (4096 + 4096 + 8 + 8)
#define SMEM_BYTES (SMEM_FLOATS * 4)

// GEMV with 8 batch-accumulators and double-buffered weight prefetch.
template<int KD>
__device__ __forceinline__ void gemv_acc8(const float* __restrict__ Wcol,
                                          const float* __restrict__ xs,
                                          float acc[8])
{
    float wreg[8];
    #pragma unroll
    for (int j = 0; j < 8; j++) wreg[j] = __ldg(&Wcol[j << 8]);
    #pragma unroll 1
    for (int c0 = 0; c0 < KD; c0 += 8) {
        float wnxt[8];
        if (c0 + 8 < KD) {
            #pragma unroll
            for (int j = 0; j < 8; j++) wnxt[j] = __ldg(&Wcol[(c0 + 8 + j) << 8]);
        }
        #pragma unroll
        for (int j = 0; j < 8; j++) {
            float4 xa = *(const float4*)&xs[(c0 + j) * 8 + 0];
            float4 xb = *(const float4*)&xs[(c0 + j) * 8 + 4];
            float wv = wreg[j];
            acc[0] += xa.x * wv; acc[1] += xa.y * wv;
            acc[2] += xa.z * wv; acc[3] += xa.w * wv;
            acc[4] += xb.x * wv; acc[5] += xb.y * wv;
            acc[6] += xb.z * wv; acc[7] += xb.w * wv;
        }
        #pragma unroll
        for (int j = 0; j < 8; j++) wreg[j] = wnxt[j];
    }
}

// 32 neighbors: online softmax + register-resident weighted accumulation,
// next-row prefetch overlaps the shuffle-reduce/exp chain.
__device__ __forceinline__ void attn_seg32(
    const float* __restrict__ relb, const float* __restrict__ nodeb,
    const float4 kq0, const float4 kq1, const float4 kq2, const float4 kq3,
    int lane, float qbk, float& m, float& ssum, float wacc[16])
{
    const float* pr = relb + 4 * lane;
    const float* pn = nodeb + 4 * lane;
    float4 A0 = *(const float4*)(pr);
    float4 A1 = *(const float4*)(pr + 128);
    float4 A2 = *(const float4*)(pn);
    float4 A3 = *(const float4*)(pn + 128);
    #pragma unroll 1
    for (int n = 0; n < 32; n++) {
        float4 B0, B1, B2, B3;
        if (n + 1 < 32) {
            const float* r = pr + (n + 1) * 256;
            const float* d = pn + (n + 1) * 256;
            B0 = *(const float4*)(r);
            B1 = *(const float4*)(r + 128);
            B2 = *(const float4*)(d);
            B3 = *(const float4*)(d + 128);
        }
        float p0 = A0.x * kq0.x + A0.y * kq0.y + A0.z * kq0.z + A0.w * kq0.w;
        float p1 = A1.x * kq1.x + A1.y * kq1.y + A1.z * kq1.z + A1.w * kq1.w;
        float p2 = A2.x * kq2.x + A2.y * kq2.y + A2.z * kq2.z + A2.w * kq2.w;
        float p3 = A3.x * kq3.x + A3.y * kq3.y + A3.z * kq3.z + A3.w * kq3.w;
        float p = (p0 + p1) + (p2 + p3);
        #pragma unroll
        for (int o = 16; o; o >>= 1) p += __shfl_xor_sync(0xffffffffu, p, o);
        float sn = (p + qbk) * 0.0625f;      // / sqrt(256)
        if (sn > m) {                        // warp-uniform
            float sc = __expf(m - sn);
            ssum *= sc;
            #pragma unroll
            for (int j = 0; j < 16; j++) wacc[j] *= sc;
            m = sn;
        }
        float e = __expf(sn - m);
        ssum += e;
        wacc[0]  += e * A0.x; wacc[1]  += e * A0.y; wacc[2]  += e * A0.z; wacc[3]  += e * A0.w;
        wacc[4]  += e * A1.x; wacc[5]  += e * A1.y; wacc[6]  += e * A1.z; wacc[7]  += e * A1.w;
        wacc[8]  += e * A2.x; wacc[9]  += e * A2.y; wacc[10] += e * A2.z; wacc[11] += e * A2.w;
        wacc[12] += e * A3.x; wacc[13] += e * A3.y; wacc[14] += e * A3.z; wacc[15] += e * A3.w;
        A0 = B0; A1 = B1; A2 = B2; A3 = B3;
    }
}

__global__ __launch_bounds__(256, 3)
void superedge_kernel(
    const float* __restrict__ mnode0, const float* __restrict__ mnode1,
    const float* __restrict__ dnode0, const float* __restrict__ dnode1,
    const float* __restrict__ mrel0,  const float* __restrict__ drel0,
    const float* __restrict__ W_edge, const float* __restrict__ b_edge,
    const float* __restrict__ Wq,     const float* __restrict__ bq,
    const float* __restrict__ bk,
    const float* __restrict__ Wv,     const float* __restrict__ bv,
    float* __restrict__ out)
{
    extern __shared__ float smem[];
    float* bufA = smem;                 // [512][G]  x, later wn
    float* ee_s = bufA + 512 * G;       // [256][G]
    float* q_s  = ee_s + 256 * G;       // [256][G]
    float* kq_s = ee_s;                 // OVERLAY [G][512] (ee+q dead)
    float* qbk_s = q_s + 256 * G;       // [G]

    const int tid = threadIdx.x;
    const int b0 = blockIdx.x * G;
    const int w = tid >> 5, lane = tid & 31;

    // ---------------- Phase 1: x = [mnode0 | dnode0] -> bufA[c][g]
    #pragma unroll
    for (int g = 0; g < G; g++) {
        int b = b0 + g;
        bufA[tid * G + g]         = mnode0[(size_t)b * 256 + tid];
        bufA[(tid + 256) * G + g] = dnode0[(size_t)b * 256 + tid];
    }
    __syncthreads();

    float acc[8];

    // ---------------- Phase 2: edge_emb[h=tid] = relu(x @ W_edge + b_edge)
    {
        float bias = b_edge[tid];
        #pragma unroll
        for (int g = 0; g < G; g++) acc[g] = bias;
        gemv_acc8<512>(W_edge + tid, bufA, acc);
        #pragma unroll
        for (int g = 0; g < G; g++) {
            float v = fmaxf(acc[g], 0.0f);
            ee_s[tid * G + g] = v;
            out[(size_t)(b0 + g) * 512 + tid] = v;   // first half of output
        }
    }
    __syncthreads();

    // ---------------- Phase 3: q[h=tid] = ee @ Wq + bq
    {
        float bias = bq[tid];
        #pragma unroll
        for (int g = 0; g < G; g++) acc[g] = bias;
        gemv_acc8<256>(Wq + tid, ee_s, acc);
        #pragma unroll
        for (int g = 0; g < G; g++) q_s[tid * G + g] = acc[g];
    }
    __syncthreads();

    // ---------------- qbk[g] = q_g . bk (warp w -> g = w)
    {
        float p = 0.0f;
        #pragma unroll
        for (int j = 0; j < 8; j++) {
            int h = lane + (j << 5);
            p += q_s[h * G + w] * bk[h];
        }
        #pragma unroll
        for (int o = 16; o; o >>= 1) p += __shfl_xor_sync(0xffffffffu, p, o);
        if (lane == 0) qbk_s[w] = p;
    }

    // ---------------- Phase 4: kq[c] = sum_h WkT[h][c] * q[h]  (2 cols/thread, prefetch d=4)
    float kqa[16];
    {
        #pragma unroll
        for (int i = 0; i < 16; i++) kqa[i] = 0.0f;
        const float* Wc0 = g_WkT + tid;        // col tid
        const float* Wc1 = g_WkT + tid + 256;  // col tid+256
        float w0b[4], w1b[4];
        #pragma unroll
        for (int j = 0; j < 4; j++) {
            w0b[j] = __ldg(&Wc0[j << 9]);
            w1b[j] = __ldg(&Wc1[j << 9]);
        }
        #pragma unroll 1
        for (int h0 = 0; h0 < 256; h0 += 4) {
            float w0n[4], w1n[4];
            if (h0 + 4 < 256) {
                #pragma unroll
                for (int j = 0; j < 4; j++) {
                    w0n[j] = __ldg(&Wc0[(h0 + 4 + j) << 9]);
                    w1n[j] = __ldg(&Wc1[(h0 + 4 + j) << 9]);
                }
            }
            #pragma unroll
            for (int j = 0; j < 4; j++) {
                int h = h0 + j;
                float4 qa = *(const float4*)&q_s[h * G + 0];
                float4 qb = *(const float4*)&q_s[h * G + 4];
                float wv0 = w0b[j], wv1 = w1b[j];
                kqa[0] += qa.x * wv0; kqa[1] += qa.y * wv0;
                kqa[2] += qa.z * wv0; kqa[3] += qa.w * wv0;
                kqa[4] += qb.x * wv0; kqa[5] += qb.y * wv0;
                kqa[6] += qb.z * wv0; kqa[7] += qb.w * wv0;
                kqa[8]  += qa.x * wv1; kqa[9]  += qa.y * wv1;
                kqa[10] += qa.z * wv1; kqa[11] += qa.w * wv1;
                kqa[12] += qb.x * wv1; kqa[13] += qb.y * wv1;
                kqa[14] += qb.z * wv1; kqa[15] += qb.w * wv1;
            }
            #pragma unroll
            for (int j = 0; j < 4; j++) { w0b[j] = w0n[j]; w1b[j] = w1n[j]; }
        }
    }
    __syncthreads();    // all reads of q/ee done before overlay write
    #pragma unroll
    for (int g = 0; g < G; g++) {
        kq_s[g * 512 + tid]       = kqa[g];
        kq_s[g * 512 + tid + 256] = kqa[8 + g];
    }
    __syncthreads();

    // ---------------- Phase 5: warp w owns batch b0+w, online softmax, reg accumulation
    {
        const int b = b0 + w;
        const float* kqg = kq_s + w * 512;
        const float qbk = qbk_s[w];

        float4 kq0 = *(const float4*)&kqg[4 * lane];
        float4 kq1 = *(const float4*)&kqg[128 + 4 * lane];
        float4 kq2 = *(const float4*)&kqg[256 + 4 * lane];
        float4 kq3 = *(const float4*)&kqg[384 + 4 * lane];

        float m = -CUDART_INF_F, ssum = 0.0f;
        float wacc[16];
        #pragma unroll
        for (int j = 0; j < 16; j++) wacc[j] = 0.0f;

        attn_seg32(mrel0 + (size_t)b * 32 * 256, mnode1 + (size_t)b * 32 * 256,
                   kq0, kq1, kq2, kq3, lane, qbk, m, ssum, wacc);
        attn_seg32(drel0 + (size_t)b * 32 * 256, dnode1 + (size_t)b * 32 * 256,
                   kq0, kq1, kq2, kq3, lane, qbk, m, ssum, wacc);

        float inv = 1.0f / ssum;
        // wacc[ch*4+j] holds c = ch*128 + 4*lane + j   (ch: 0,1 = rel; 2,3 = node)
        #pragma unroll
        for (int ch = 0; ch < 4; ch++)
            #pragma unroll
            for (int j = 0; j < 4; j++)
                bufA[(ch * 128 + 4 * lane + j) * G + w] = wacc[ch * 4 + j] * inv;
    }
    __syncthreads();

    // ---------------- Phase 6: local_edge[h=tid] = wn @ Wv + bv
    {
        float bias = bv[tid];
        #pragma unroll
        for (int g = 0; g < G; g++) acc[g] = bias;
        gemv_acc8<512>(Wv + tid, bufA, acc);
        #pragma unroll
        for (int g = 0; g < G; g++)
            out[(size_t)(b0 + g) * 512 + 256 + tid] = acc[g];  // second half
    }
}

extern "C" void kernel_launch(void* const* d_in, const int* in_sizes, int n_in,
                              void* d_out, int out_size) {
    const float* mnode0 = (const float*)d_in[0];
    const float* mnode1 = (const float*)d_in[1];
    const float* dnode0 = (const float*)d_in[2];
    const float* dnode1 = (const float*)d_in[3];
    const float* mrel0  = (const float*)d_in[4];
    const float* drel0  = (const float*)d_in[5];
    const float* W_edge = (const float*)d_in[6];
    const float* b_edge = (const float*)d_in[7];
    const float* Wq     = (const float*)d_in[8];
    const float* bq     = (const float*)d_in[9];
    const float* Wk     = (const float*)d_in[10];
    const float* bk     = (const float*)d_in[11];
    const float* Wv     = (const float*)d_in[12];
    const float* bv     = (const float*)d_in[13];
    float* out = (float*)d_out;

    cudaFuncSetAttribute(superedge_kernel,
                         cudaFuncAttributeMaxDynamicSharedMemorySize, SMEM_BYTES);

    wkT_kernel<<<512, 256>>>(Wk);
    superedge_kernel<<<NB / G, THREADS, SMEM_BYTES>>>(
        mnode0, mnode1, dnode0, dnode1, mrel0, drel0,
        W_edge, b_edge, Wq, bq, bk, Wv, bv, out);
}

// round 5
// speedup vs baseline: 1.3669x; 1.3669x over previous
#include <cuda_runtime.h>
#include <math_constants.h>

#define G 8
#define NB 8192
#define THREADS 256

// Wk transposed: [h][c] = Wk[c][h], 256x512 floats
__device__ float g_WkT[256 * 512];

__global__ void wkT_kernel(const float* __restrict__ Wk) {
    int idx = blockIdx.x * blockDim.x + threadIdx.x;
    if (idx < 512 * 256) {
        int c = idx >> 8;      // 0..511
        int h = idx & 255;     // 0..255
        g_WkT[h * 512 + c] = Wk[idx];
    }
}

// Dynamic smem (floats):
//   bufA : [512][G]  (x concat, later wn)                    4096 f
//   eq   : [512][G]  (ee [0:256), q [256:512)) -> overlay kq 4096 f
#define SMEM_FLOATS (4096 + 4096 + 16)
#define SMEM_BYTES (SMEM_FLOATS * 4)

// GEMV with 8 batch-accumulators and double-buffered weight prefetch.
template<int KD>
__device__ __forceinline__ void gemv_acc8(const float* __restrict__ Wcol,
                                          const float* __restrict__ xs,
                                          float acc[8])
{
    float wreg[8];
    #pragma unroll
    for (int j = 0; j < 8; j++) wreg[j] = __ldg(&Wcol[j << 8]);
    #pragma unroll 1
    for (int c0 = 0; c0 < KD; c0 += 8) {
        float wnxt[8];
        if (c0 + 8 < KD) {
            #pragma unroll
            for (int j = 0; j < 8; j++) wnxt[j] = __ldg(&Wcol[(c0 + 8 + j) << 8]);
        }
        #pragma unroll
        for (int j = 0; j < 8; j++) {
            float4 xa = *(const float4*)&xs[(c0 + j) * 8 + 0];
            float4 xb = *(const float4*)&xs[(c0 + j) * 8 + 4];
            float wv = wreg[j];
            acc[0] += xa.x * wv; acc[1] += xa.y * wv;
            acc[2] += xa.z * wv; acc[3] += xa.w * wv;
            acc[4] += xb.x * wv; acc[5] += xb.y * wv;
            acc[6] += xb.z * wv; acc[7] += xb.w * wv;
        }
        #pragma unroll
        for (int j = 0; j < 8; j++) wreg[j] = wnxt[j];
    }
}

// 32 neighbors: online softmax, accumulate straight from the score-load regs.
__device__ __forceinline__ void attn_seg32(
    const float* __restrict__ relb, const float* __restrict__ nodeb,
    const float4 kq0, const float4 kq1, const float4 kq2, const float4 kq3,
    int lane, float& m, float& ssum, float wacc[16])
{
    const float* pr = relb + 4 * lane;
    const float* pn = nodeb + 4 * lane;
    #pragma unroll 1
    for (int n = 0; n < 32; n++) {
        float4 A0 = *(const float4*)(pr + n * 256);
        float4 A1 = *(const float4*)(pr + n * 256 + 128);
        float4 A2 = *(const float4*)(pn + n * 256);
        float4 A3 = *(const float4*)(pn + n * 256 + 128);

        float p0 = A0.x * kq0.x + A0.y * kq0.y + A0.z * kq0.z + A0.w * kq0.w;
        float p1 = A1.x * kq1.x + A1.y * kq1.y + A1.z * kq1.z + A1.w * kq1.w;
        float p2 = A2.x * kq2.x + A2.y * kq2.y + A2.z * kq2.z + A2.w * kq2.w;
        float p3 = A3.x * kq3.x + A3.y * kq3.y + A3.z * kq3.z + A3.w * kq3.w;
        float p = (p0 + p1) + (p2 + p3);
        #pragma unroll
        for (int o = 16; o; o >>= 1) p += __shfl_xor_sync(0xffffffffu, p, o);

        float sn = p * 0.0625f;              // / sqrt(256); q.bk shift cancels in softmax
        if (sn > m) {                        // warp-uniform branch
            float sc = __expf(m - sn);
            ssum *= sc;
            #pragma unroll
            for (int j = 0; j < 16; j++) wacc[j] *= sc;
            m = sn;
        }
        float e = __expf(sn - m);
        ssum += e;
        wacc[0]  += e * A0.x; wacc[1]  += e * A0.y; wacc[2]  += e * A0.z; wacc[3]  += e * A0.w;
        wacc[4]  += e * A1.x; wacc[5]  += e * A1.y; wacc[6]  += e * A1.z; wacc[7]  += e * A1.w;
        wacc[8]  += e * A2.x; wacc[9]  += e * A2.y; wacc[10] += e * A2.z; wacc[11] += e * A2.w;
        wacc[12] += e * A3.x; wacc[13] += e * A3.y; wacc[14] += e * A3.z; wacc[15] += e * A3.w;
    }
}

__global__ __launch_bounds__(256, 4)
void superedge_kernel(
    const float* __restrict__ mnode0, const float* __restrict__ mnode1,
    const float* __restrict__ dnode0, const float* __restrict__ dnode1,
    const float* __restrict__ mrel0,  const float* __restrict__ drel0,
    const float* __restrict__ W_edge, const float* __restrict__ b_edge,
    const float* __restrict__ Wq,     const float* __restrict__ bq,
    const float* __restrict__ bk,
    const float* __restrict__ Wv,     const float* __restrict__ bv,
    float* __restrict__ out)
{
    extern __shared__ float smem[];
    float* bufA = smem;                 // [512][G]  x, later wn
    float* ee_s = bufA + 512 * G;       // [256][G]
    float* q_s  = ee_s + 256 * G;       // [256][G]
    float* kq_s = ee_s;                 // OVERLAY [G][512] (ee+q dead)

    const int tid = threadIdx.x;
    const int b0 = blockIdx.x * G;
    const int w = tid >> 5, lane = tid & 31;

    // ---------------- Phase 1: x = [mnode0 | dnode0] -> bufA[c][g]
    #pragma unroll
    for (int g = 0; g < G; g++) {
        int b = b0 + g;
        bufA[tid * G + g]         = mnode0[(size_t)b * 256 + tid];
        bufA[(tid + 256) * G + g] = dnode0[(size_t)b * 256 + tid];
    }
    __syncthreads();

    float acc[8];

    // ---------------- Phase 2: edge_emb[h=tid] = relu(x @ W_edge + b_edge)
    {
        float bias = b_edge[tid];
        #pragma unroll
        for (int g = 0; g < G; g++) acc[g] = bias;
        gemv_acc8<512>(W_edge + tid, bufA, acc);
        #pragma unroll
        for (int g = 0; g < G; g++) {
            float v = fmaxf(acc[g], 0.0f);
            ee_s[tid * G + g] = v;
            out[(size_t)(b0 + g) * 512 + tid] = v;   // first half of output
        }
    }
    __syncthreads();

    // ---------------- Phase 3: q[h=tid] = ee @ Wq + bq
    {
        float bias = bq[tid];
        #pragma unroll
        for (int g = 0; g < G; g++) acc[g] = bias;
        gemv_acc8<256>(Wq + tid, ee_s, acc);
        #pragma unroll
        for (int g = 0; g < G; g++) q_s[tid * G + g] = acc[g];
    }
    __syncthreads();

    // ---------------- Phase 4: kq[c] = sum_h WkT[h][c] * q[h]  (2 cols/thread, prefetch d=4)
    float kqa[16];
    {
        #pragma unroll
        for (int i = 0; i < 16; i++) kqa[i] = 0.0f;
        const float* Wc0 = g_WkT + tid;        // col tid
        const float* Wc1 = g_WkT + tid + 256;  // col tid+256
        float w0b[4], w1b[4];
        #pragma unroll
        for (int j = 0; j < 4; j++) {
            w0b[j] = __ldg(&Wc0[j << 9]);
            w1b[j] = __ldg(&Wc1[j << 9]);
        }
        #pragma unroll 1
        for (int h0 = 0; h0 < 256; h0 += 4) {
            float w0n[4], w1n[4];
            if (h0 + 4 < 256) {
                #pragma unroll
                for (int j = 0; j < 4; j++) {
                    w0n[j] = __ldg(&Wc0[(h0 + 4 + j) << 9]);
                    w1n[j] = __ldg(&Wc1[(h0 + 4 + j) << 9]);
                }
            }
            #pragma unroll
            for (int j = 0; j < 4; j++) {
                int h = h0 + j;
                float4 qa = *(const float4*)&q_s[h * G + 0];
                float4 qb = *(const float4*)&q_s[h * G + 4];
                float wv0 = w0b[j], wv1 = w1b[j];
                kqa[0] += qa.x * wv0; kqa[1] += qa.y * wv0;
                kqa[2] += qa.z * wv0; kqa[3] += qa.w * wv0;
                kqa[4] += qb.x * wv0; kqa[5] += qb.y * wv0;
                kqa[6] += qb.z * wv0; kqa[7] += qb.w * wv0;
                kqa[8]  += qa.x * wv1; kqa[9]  += qa.y * wv1;
                kqa[10] += qa.z * wv1; kqa[11] += qa.w * wv1;
                kqa[12] += qb.x * wv1; kqa[13] += qb.y * wv1;
                kqa[14] += qb.z * wv1; kqa[15] += qb.w * wv1;
            }
            #pragma unroll
            for (int j = 0; j < 4; j++) { w0b[j] = w0n[j]; w1b[j] = w1n[j]; }
        }
    }
    __syncthreads();    // all reads of q/ee done before overlay write
    #pragma unroll
    for (int g = 0; g < G; g++) {
        kq_s[g * 512 + tid]       = kqa[g];
        kq_s[g * 512 + tid + 256] = kqa[8 + g];
    }
    __syncthreads();

    // ---------------- Phase 5: warp w owns batch b0+w, online softmax, reg accumulation
    {
        const int b = b0 + w;
        const float* kqg = kq_s + w * 512;

        float4 kq0 = *(const float4*)&kqg[4 * lane];
        float4 kq1 = *(const float4*)&kqg[128 + 4 * lane];
        float4 kq2 = *(const float4*)&kqg[256 + 4 * lane];
        float4 kq3 = *(const float4*)&kqg[384 + 4 * lane];

        float m = -CUDART_INF_F, ssum = 0.0f;
        float wacc[16];
        #pragma unroll
        for (int j = 0; j < 16; j++) wacc[j] = 0.0f;

        attn_seg32(mrel0 + (size_t)b * 32 * 256, mnode1 + (size_t)b * 32 * 256,
                   kq0, kq1, kq2, kq3, lane, m, ssum, wacc);
        attn_seg32(drel0 + (size_t)b * 32 * 256, dnode1 + (size_t)b * 32 * 256,
                   kq0, kq1, kq2, kq3, lane, m, ssum, wacc);

        float inv = 1.0f / ssum;
        // wacc[ch*4+j] holds c = ch*128 + 4*lane + j   (ch: 0,1 = rel; 2,3 = node)
        #pragma unroll
        for (int ch = 0; ch < 4; ch++)
            #pragma unroll
            for (int j = 0; j < 4; j++)
                bufA[(ch * 128 + 4 * lane + j) * G + w] = wacc[ch * 4 + j] * inv;
    }
    __syncthreads();

    // ---------------- Phase 6: local_edge[h=tid] = wn @ Wv + bv
    {
        float bias = bv[tid];
        #pragma unroll
        for (int g = 0; g < G; g++) acc[g] = bias;
        gemv_acc8<512>(Wv + tid, bufA, acc);
        #pragma unroll
        for (int g = 0; g < G; g++)
            out[(size_t)(b0 + g) * 512 + 256 + tid] = acc[g];  // second half
    }
}

extern "C" void kernel_launch(void* const* d_in, const int* in_sizes, int n_in,
                              void* d_out, int out_size) {
    const float* mnode0 = (const float*)d_in[0];
    const float* mnode1 = (const float*)d_in[1];
    const float* dnode0 = (const float*)d_in[2];
    const float* dnode1 = (const float*)d_in[3];
    const float* mrel0  = (const float*)d_in[4];
    const float* drel0  = (const float*)d_in[5];
    const float* W_edge = (const float*)d_in[6];
    const float* b_edge = (const float*)d_in[7];
    const float* Wq     = (const float*)d_in[8];
    const float* bq     = (const float*)d_in[9];
    const float* Wk     = (const float*)d_in[10];
    const float* bk     = (const float*)d_in[11];
    const float* Wv     = (const float*)d_in[12];
    const float* bv     = (const float*)d_in[13];
    float* out = (float*)d_out;

    cudaFuncSetAttribute(superedge_kernel,
                         cudaFuncAttributeMaxDynamicSharedMemorySize, SMEM_BYTES);

    wkT_kernel<<<512, 256>>>(Wk);
    superedge_kernel<<<NB / G, THREADS, SMEM_BYTES>>>(
        mnode0, mnode1, dnode0, dnode1, mrel0, drel0,
        W_edge, b_edge, Wq, bq, bk, Wv, bv, out);
}

// round 6
// speedup vs baseline: 1.4017x; 1.0254x over previous
#include <cuda_runtime.h>
#include <math_constants.h>

#define G 8
#define NB 8192
#define THREADS 256

typedef unsigned long long u64;

// ---- packed f32x2 helpers (sm_103a) ----
__device__ __forceinline__ u64 fma2(u64 a, u64 b, u64 c) {
    u64 d;
    asm("fma.rn.f32x2 %0, %1, %2, %3;" : "=l"(d) : "l"(a), "l"(b), "l"(c));
    return d;
}
__device__ __forceinline__ u64 mul2(u64 a, u64 b) {
    u64 d;
    asm("mul.rn.f32x2 %0, %1, %2;" : "=l"(d) : "l"(a), "l"(b));
    return d;
}
__device__ __forceinline__ u64 splat2(float v) {
    u64 d;
    asm("mov.b64 %0, {%1, %1};" : "=l"(d) : "f"(v));
    return d;
}
__device__ __forceinline__ float2 unpack2(u64 v) {
    float2 r;
    asm("mov.b64 {%0, %1}, %2;" : "=f"(r.x), "=f"(r.y) : "l"(v));
    return r;
}

// Wk transposed: [h][c] = Wk[c][h], 256x512 floats
__device__ float g_WkT[256 * 512];

__global__ void wkT_kernel(const float* __restrict__ Wk) {
    int idx = blockIdx.x * blockDim.x + threadIdx.x;
    if (idx < 512 * 256) {
        int c = idx >> 8;      // 0..511
        int h = idx & 255;     // 0..255
        g_WkT[h * 512 + c] = Wk[idx];
    }
}

// Dynamic smem (floats):
//   bufA : [512][G]  (x concat, later wn)                    4096 f
//   eq   : [512][G]  (ee [0:256), q [256:512)) -> overlay kq 4096 f
#define SMEM_FLOATS (4096 + 4096 + 16)
#define SMEM_BYTES (SMEM_FLOATS * 4)

// GEMV, 8 batch-accumulators as 4 packed f32x2, double-buffered weight prefetch.
template<int KD>
__device__ __forceinline__ void gemv_acc8p(const float* __restrict__ Wcol,
                                           const float* __restrict__ xs,
                                           u64 acc[4])
{
    float wreg[8];
    #pragma unroll
    for (int j = 0; j < 8; j++) wreg[j] = __ldg(&Wcol[j << 8]);
    #pragma unroll 1
    for (int c0 = 0; c0 < KD; c0 += 8) {
        float wnxt[8];
        if (c0 + 8 < KD) {
            #pragma unroll
            for (int j = 0; j < 8; j++) wnxt[j] = __ldg(&Wcol[(c0 + 8 + j) << 8]);
        }
        #pragma unroll
        for (int j = 0; j < 8; j++) {
            ulonglong2 xa = *(const ulonglong2*)&xs[(c0 + j) * 8 + 0];
            ulonglong2 xb = *(const ulonglong2*)&xs[(c0 + j) * 8 + 4];
            u64 wp = splat2(wreg[j]);
            acc[0] = fma2(xa.x, wp, acc[0]);
            acc[1] = fma2(xa.y, wp, acc[1]);
            acc[2] = fma2(xb.x, wp, acc[2]);
            acc[3] = fma2(xb.y, wp, acc[3]);
        }
        #pragma unroll
        for (int j = 0; j < 8; j++) wreg[j] = wnxt[j];
    }
}

// 32 neighbors: online softmax, packed f32x2 dots + accumulation.
__device__ __forceinline__ void attn_seg32(
    const float* __restrict__ relb, const float* __restrict__ nodeb,
    const u64 kqp[8],
    int lane, float& m, float& ssum, u64 waccp[8])
{
    const float* pr = relb + 4 * lane;
    const float* pn = nodeb + 4 * lane;
    #pragma unroll 1
    for (int n = 0; n < 32; n++) {
        ulonglong2 A0 = *(const ulonglong2*)(pr + n * 256);
        ulonglong2 A1 = *(const ulonglong2*)(pr + n * 256 + 128);
        ulonglong2 A2 = *(const ulonglong2*)(pn + n * 256);
        ulonglong2 A3 = *(const ulonglong2*)(pn + n * 256 + 128);

        u64 pp = fma2(A0.x, kqp[0], splat2(0.0f));
        pp = fma2(A0.y, kqp[1], pp);
        pp = fma2(A1.x, kqp[2], pp);
        pp = fma2(A1.y, kqp[3], pp);
        pp = fma2(A2.x, kqp[4], pp);
        pp = fma2(A2.y, kqp[5], pp);
        pp = fma2(A3.x, kqp[6], pp);
        pp = fma2(A3.y, kqp[7], pp);
        float2 pu = unpack2(pp);
        float p = pu.x + pu.y;
        #pragma unroll
        for (int o = 16; o; o >>= 1) p += __shfl_xor_sync(0xffffffffu, p, o);

        float sn = p * 0.0625f;              // / sqrt(256); q.bk shift cancels in softmax
        if (sn > m) {                        // warp-uniform branch
            float sc = __expf(m - sn);
            ssum *= sc;
            u64 scp = splat2(sc);
            #pragma unroll
            for (int j = 0; j < 8; j++) waccp[j] = mul2(waccp[j], scp);
            m = sn;
        }
        float e = __expf(sn - m);
        ssum += e;
        u64 ep = splat2(e);
        waccp[0] = fma2(ep, A0.x, waccp[0]);
        waccp[1] = fma2(ep, A0.y, waccp[1]);
        waccp[2] = fma2(ep, A1.x, waccp[2]);
        waccp[3] = fma2(ep, A1.y, waccp[3]);
        waccp[4] = fma2(ep, A2.x, waccp[4]);
        waccp[5] = fma2(ep, A2.y, waccp[5]);
        waccp[6] = fma2(ep, A3.x, waccp[6]);
        waccp[7] = fma2(ep, A3.y, waccp[7]);
    }
}

__global__ __launch_bounds__(256, 4)
void superedge_kernel(
    const float* __restrict__ mnode0, const float* __restrict__ mnode1,
    const float* __restrict__ dnode0, const float* __restrict__ dnode1,
    const float* __restrict__ mrel0,  const float* __restrict__ drel0,
    const float* __restrict__ W_edge, const float* __restrict__ b_edge,
    const float* __restrict__ Wq,     const float* __restrict__ bq,
    const float* __restrict__ bk,
    const float* __restrict__ Wv,     const float* __restrict__ bv,
    float* __restrict__ out)
{
    extern __shared__ float smem[];
    float* bufA = smem;                 // [512][G]  x, later wn
    float* ee_s = bufA + 512 * G;       // [256][G]
    float* q_s  = ee_s + 256 * G;       // [256][G]
    float* kq_s = ee_s;                 // OVERLAY [G][512] (ee+q dead)

    const int tid = threadIdx.x;
    const int b0 = blockIdx.x * G;
    const int w = tid >> 5, lane = tid & 31;

    // ---------------- Phase 1: x = [mnode0 | dnode0] -> bufA[c][g]
    #pragma unroll
    for (int g = 0; g < G; g++) {
        int b = b0 + g;
        bufA[tid * G + g]         = mnode0[(size_t)b * 256 + tid];
        bufA[(tid + 256) * G + g] = dnode0[(size_t)b * 256 + tid];
    }
    __syncthreads();

    u64 acc[4];

    // ---------------- Phase 2: edge_emb[h=tid] = relu(x @ W_edge + b_edge)
    {
        u64 bias = splat2(b_edge[tid]);
        #pragma unroll
        for (int i = 0; i < 4; i++) acc[i] = bias;
        gemv_acc8p<512>(W_edge + tid, bufA, acc);
        #pragma unroll
        for (int i = 0; i < 4; i++) {
            float2 r = unpack2(acc[i]);
            float v0 = fmaxf(r.x, 0.0f);
            float v1 = fmaxf(r.y, 0.0f);
            ee_s[tid * G + 2 * i]     = v0;
            ee_s[tid * G + 2 * i + 1] = v1;
            out[(size_t)(b0 + 2 * i) * 512 + tid]     = v0;
            out[(size_t)(b0 + 2 * i + 1) * 512 + tid] = v1;
        }
    }
    __syncthreads();

    // ---------------- Phase 3: q[h=tid] = ee @ Wq + bq
    {
        u64 bias = splat2(bq[tid]);
        #pragma unroll
        for (int i = 0; i < 4; i++) acc[i] = bias;
        gemv_acc8p<256>(Wq + tid, ee_s, acc);
        #pragma unroll
        for (int i = 0; i < 4; i++) {
            float2 r = unpack2(acc[i]);
            q_s[tid * G + 2 * i]     = r.x;
            q_s[tid * G + 2 * i + 1] = r.y;
        }
    }
    __syncthreads();

    // ---------------- Phase 4: kq[c] = sum_h WkT[h][c] * q[h]  (2 cols/thread, prefetch d=4)
    u64 kqp[8];   // [0..3] col tid (g-pairs), [4..7] col tid+256
    {
        #pragma unroll
        for (int i = 0; i < 8; i++) kqp[i] = splat2(0.0f);
        const float* Wc0 = g_WkT + tid;        // col tid
        const float* Wc1 = g_WkT + tid + 256;  // col tid+256
        float w0b[4], w1b[4];
        #pragma unroll
        for (int j = 0; j < 4; j++) {
            w0b[j] = __ldg(&Wc0[j << 9]);
            w1b[j] = __ldg(&Wc1[j << 9]);
        }
        #pragma unroll 1
        for (int h0 = 0; h0 < 256; h0 += 4) {
            float w0n[4], w1n[4];
            if (h0 + 4 < 256) {
                #pragma unroll
                for (int j = 0; j < 4; j++) {
                    w0n[j] = __ldg(&Wc0[(h0 + 4 + j) << 9]);
                    w1n[j] = __ldg(&Wc1[(h0 + 4 + j) << 9]);
                }
            }
            #pragma unroll
            for (int j = 0; j < 4; j++) {
                int h = h0 + j;
                ulonglong2 qa = *(const ulonglong2*)&q_s[h * G + 0];
                ulonglong2 qb = *(const ulonglong2*)&q_s[h * G + 4];
                u64 wp0 = splat2(w0b[j]);
                u64 wp1 = splat2(w1b[j]);
                kqp[0] = fma2(qa.x, wp0, kqp[0]);
                kqp[1] = fma2(qa.y, wp0, kqp[1]);
                kqp[2] = fma2(qb.x, wp0, kqp[2]);
                kqp[3] = fma2(qb.y, wp0, kqp[3]);
                kqp[4] = fma2(qa.x, wp1, kqp[4]);
                kqp[5] = fma2(qa.y, wp1, kqp[5]);
                kqp[6] = fma2(qb.x, wp1, kqp[6]);
                kqp[7] = fma2(qb.y, wp1, kqp[7]);
            }
            #pragma unroll
            for (int j = 0; j < 4; j++) { w0b[j] = w0n[j]; w1b[j] = w1n[j]; }
        }
    }
    __syncthreads();    // all reads of q/ee done before overlay write
    #pragma unroll
    for (int i = 0; i < 4; i++) {
        float2 r0 = unpack2(kqp[i]);       // col tid, g = 2i, 2i+1
        float2 r1 = unpack2(kqp[4 + i]);   // col tid+256
        kq_s[(2 * i) * 512 + tid]           = r0.x;
        kq_s[(2 * i + 1) * 512 + tid]       = r0.y;
        kq_s[(2 * i) * 512 + tid + 256]     = r1.x;
        kq_s[(2 * i + 1) * 512 + tid + 256] = r1.y;
    }
    __syncthreads();

    // ---------------- Phase 5: warp w owns batch b0+w, online softmax, packed accumulation
    {
        const int b = b0 + w;
        const float* kqg = kq_s + w * 512;

        u64 kqr[8];
        {
            ulonglong2 k0 = *(const ulonglong2*)&kqg[4 * lane];
            ulonglong2 k1 = *(const ulonglong2*)&kqg[128 + 4 * lane];
            ulonglong2 k2 = *(const ulonglong2*)&kqg[256 + 4 * lane];
            ulonglong2 k3 = *(const ulonglong2*)&kqg[384 + 4 * lane];
            kqr[0] = k0.x; kqr[1] = k0.y;
            kqr[2] = k1.x; kqr[3] = k1.y;
            kqr[4] = k2.x; kqr[5] = k2.y;
            kqr[6] = k3.x; kqr[7] = k3.y;
        }

        float m = -CUDART_INF_F, ssum = 0.0f;
        u64 waccp[8];
        #pragma unroll
        for (int j = 0; j < 8; j++) waccp[j] = splat2(0.0f);

        attn_seg32(mrel0 + (size_t)b * 32 * 256, mnode1 + (size_t)b * 32 * 256,
                   kqr, lane, m, ssum, waccp);
        attn_seg32(drel0 + (size_t)b * 32 * 256, dnode1 + (size_t)b * 32 * 256,
                   kqr, lane, m, ssum, waccp);

        u64 invp = splat2(1.0f / ssum);
        // waccp[ch*2+k] holds c = ch*128 + 4*lane + 2k (+1)
        #pragma unroll
        for (int ch = 0; ch < 4; ch++) {
            #pragma unroll
            for (int k = 0; k < 2; k++) {
                float2 f = unpack2(mul2(waccp[ch * 2 + k], invp));
                bufA[(ch * 128 + 4 * lane + 2 * k) * G + w]     = f.x;
                bufA[(ch * 128 + 4 * lane + 2 * k + 1) * G + w] = f.y;
            }
        }
    }
    __syncthreads();

    // ---------------- Phase 6: local_edge[h=tid] = wn @ Wv + bv
    {
        u64 bias = splat2(bv[tid]);
        #pragma unroll
        for (int i = 0; i < 4; i++) acc[i] = bias;
        gemv_acc8p<512>(Wv + tid, bufA, acc);
        #pragma unroll
        for (int i = 0; i < 4; i++) {
            float2 r = unpack2(acc[i]);
            out[(size_t)(b0 + 2 * i) * 512 + 256 + tid]     = r.x;
            out[(size_t)(b0 + 2 * i + 1) * 512 + 256 + tid] = r.y;
        }
    }
}

extern "C" void kernel_launch(void* const* d_in, const int* in_sizes, int n_in,
                              void* d_out, int out_size) {
    const float* mnode0 = (const float*)d_in[0];
    const float* mnode1 = (const float*)d_in[1];
    const float* dnode0 = (const float*)d_in[2];
    const float* dnode1 = (const float*)d_in[3];
    const float* mrel0  = (const float*)d_in[4];
    const float* drel0  = (const float*)d_in[5];
    const float* W_edge = (const float*)d_in[6];
    const float* b_edge = (const float*)d_in[7];
    const float* Wq     = (const float*)d_in[8];
    const float* bq     = (const float*)d_in[9];
    const float* Wk     = (const float*)d_in[10];
    const float* bk     = (const float*)d_in[11];
    const float* Wv     = (const float*)d_in[12];
    const float* bv     = (const float*)d_in[13];
    float* out = (float*)d_out;

    cudaFuncSetAttribute(superedge_kernel,
                         cudaFuncAttributeMaxDynamicSharedMemorySize, SMEM_BYTES);

    wkT_kernel<<<512, 256>>>(Wk);
    superedge_kernel<<<NB / G, THREADS, SMEM_BYTES>>>(
        mnode0, mnode1, dnode0, dnode1, mrel0, drel0,
        W_edge, b_edge, Wq, bq, bk, Wv, bv, out);
}